// round 11
// baseline (speedup 1.0000x reference)
#include <cuda_runtime.h>

// Problem constants (fixed by the reference setup)
#define BZ_ 8
#define NF_ 10000
#define D_  16
#define H_  512
#define W_  512
#define HW_ (H_ * W_)        // 262144 = 2^18
#define NPIX (BZ_ * HW_)     // 2097152
#define CH_ (D_ + 1)         // 17 output channels
#define TPB 256
#define TILE_PX 256          // px per tile (8 warps x 32 px)
#define TILES_PER_BLOCK 8
#define NBLOCKS (NPIX / (TILE_PX * TILES_PER_BLOCK))   // 1024

__global__ void __launch_bounds__(TPB, 2)     // <=128 regs, 2 blocks/SM
render_kernel(const float4* __restrict__ attrs,   // [BZ*NF, 12] float4 (3 verts x 16 floats)
              const float*  __restrict__ baryw,   // [BZ, H, W, 3]
              const int*    __restrict__ tri,     // [BZ, H, W]
              float*        __restrict__ out)     // [BZ, 17, H, W]
{
    const int lane = threadIdx.x & 31;
    const int q    = lane & 3;                     // channel slice 4q..4q+3
    const int g    = lane >> 2;                    // pixel group within warp
    const int warp = threadIdx.x >> 5;
    const int woff = warp * 32 + 4 * g;            // thread's group offset within tile

    const int tile0 = blockIdx.x * TILES_PER_BLOCK;

    // ---- prologue: start first tile's loads ----
    int4 t4 = *(const int4*)(tri + tile0 * TILE_PX + woff);
    const float4* bb = (const float4*)(baryw + 3 * (tile0 * TILE_PX + woff));
    float4 b0 = bb[0], b1 = bb[1], b2 = bb[2];

    const float4* v0 = attrs + ((t4.x < 0) ? 0 : t4.x) * 12 + q;
    const float4* v1 = attrs + ((t4.y < 0) ? 0 : t4.y) * 12 + q;
    const float4* v2 = attrs + ((t4.z < 0) ? 0 : t4.z) * 12 + q;
    const float4* v3 = attrs + ((t4.w < 0) ? 0 : t4.w) * 12 + q;
    float4 a0 = v0[0], m0 = v0[4], c0 = v0[8];
    float4 a1 = v1[0], m1 = v1[4], c1 = v1[8];
    float4 a2 = v2[0], m2 = v2[4], c2 = v2[8];
    float4 a3 = v3[0], m3 = v3[4], c3 = v3[8];

    float e0 = (t4.x < 0) ? 0.0f : 1.0f;
    float e1 = (t4.y < 0) ? 0.0f : 1.0f;
    float e2 = (t4.z < 0) ? 0.0f : 1.0f;
    float e3 = (t4.w < 0) ? 0.0f : 1.0f;

    float w00 = b0.x * e0, w01 = b0.y * e0, w02 = b0.z * e0;
    float w10 = b0.w * e1, w11 = b1.x * e1, w12 = b1.y * e1;
    float w20 = b1.z * e2, w21 = b1.w * e2, w22 = b2.x * e2;
    float w30 = b2.y * e3, w31 = b2.z * e3, w32 = b2.w * e3;

    #pragma unroll 1
    for (int it = 0; it < TILES_PER_BLOCK; it++) {
        const int  tile = tile0 + it;
        const bool hn   = (it + 1) < TILES_PER_BLOCK;

        // 1. prefetch next tile's meta (covered by blend+store below)
        int4 t4n;
        float4 b0n, b1n, b2n;
        if (hn) {
            const int pn = (tile + 1) * TILE_PX + woff;
            t4n = *(const int4*)(tri + pn);
            const float4* bbn = (const float4*)(baryw + 3 * pn);
            b0n = bbn[0]; b1n = bbn[1]; b2n = bbn[2];
        }

        // 2. blend current tile (gathers were issued a full iteration ago)
        float4 r0, r1, r2, r3;
        r0.x = fmaf(w00, a0.x, fmaf(w01, m0.x, w02 * c0.x));
        r0.y = fmaf(w00, a0.y, fmaf(w01, m0.y, w02 * c0.y));
        r0.z = fmaf(w00, a0.z, fmaf(w01, m0.z, w02 * c0.z));
        r0.w = fmaf(w00, a0.w, fmaf(w01, m0.w, w02 * c0.w));
        r1.x = fmaf(w10, a1.x, fmaf(w11, m1.x, w12 * c1.x));
        r1.y = fmaf(w10, a1.y, fmaf(w11, m1.y, w12 * c1.y));
        r1.z = fmaf(w10, a1.z, fmaf(w11, m1.z, w12 * c1.z));
        r1.w = fmaf(w10, a1.w, fmaf(w11, m1.w, w12 * c1.w));
        r2.x = fmaf(w20, a2.x, fmaf(w21, m2.x, w22 * c2.x));
        r2.y = fmaf(w20, a2.y, fmaf(w21, m2.y, w22 * c2.y));
        r2.z = fmaf(w20, a2.z, fmaf(w21, m2.z, w22 * c2.z));
        r2.w = fmaf(w20, a2.w, fmaf(w21, m2.w, w22 * c2.w));
        r3.x = fmaf(w30, a3.x, fmaf(w31, m3.x, w32 * c3.x));
        r3.y = fmaf(w30, a3.y, fmaf(w31, m3.y, w32 * c3.y));
        r3.z = fmaf(w30, a3.z, fmaf(w31, m3.z, w32 * c3.z));
        r3.w = fmaf(w30, a3.w, fmaf(w31, m3.w, w32 * c3.w));

        // 3. stores: register transpose -> one STG.128 per channel plane
        const int base = tile * TILE_PX + warp * 32;
        const int n    = base >> 18;                 // base / HW_
        const int pix0 = (base & (HW_ - 1)) + 4 * g;
        float* op = out + (size_t)n * CH_ * HW_ + pix0;

        *(float4*)(op + (size_t)(4 * q + 0) * HW_) = make_float4(r0.x, r1.x, r2.x, r3.x);
        *(float4*)(op + (size_t)(4 * q + 1) * HW_) = make_float4(r0.y, r1.y, r2.y, r3.y);
        *(float4*)(op + (size_t)(4 * q + 2) * HW_) = make_float4(r0.z, r1.z, r2.z, r3.z);
        *(float4*)(op + (size_t)(4 * q + 3) * HW_) = make_float4(r0.w, r1.w, r2.w, r3.w);
        if (q == 0)
            *(float4*)(op + (size_t)D_ * HW_) = make_float4(e0, e1, e2, e3);  // visibility

        if (!hn) break;

        // 4. issue next tile's gathers (consumed next iteration)
        const float4* n0 = attrs + ((t4n.x < 0) ? 0 : t4n.x) * 12 + q;
        const float4* n1 = attrs + ((t4n.y < 0) ? 0 : t4n.y) * 12 + q;
        const float4* n2 = attrs + ((t4n.z < 0) ? 0 : t4n.z) * 12 + q;
        const float4* n3 = attrs + ((t4n.w < 0) ? 0 : t4n.w) * 12 + q;
        a0 = n0[0]; m0 = n0[4]; c0 = n0[8];
        a1 = n1[0]; m1 = n1[4]; c1 = n1[8];
        a2 = n2[0]; m2 = n2[4]; c2 = n2[8];
        a3 = n3[0]; m3 = n3[4]; c3 = n3[8];

        // 5. next weights (branchless background)
        e0 = (t4n.x < 0) ? 0.0f : 1.0f;
        e1 = (t4n.y < 0) ? 0.0f : 1.0f;
        e2 = (t4n.z < 0) ? 0.0f : 1.0f;
        e3 = (t4n.w < 0) ? 0.0f : 1.0f;
        w00 = b0n.x * e0; w01 = b0n.y * e0; w02 = b0n.z * e0;
        w10 = b0n.w * e1; w11 = b1n.x * e1; w12 = b1n.y * e1;
        w20 = b1n.z * e2; w21 = b1n.w * e2; w22 = b2n.x * e2;
        w30 = b2n.y * e3; w31 = b2n.z * e3; w32 = b2n.w * e3;
    }
}

extern "C" void kernel_launch(void* const* d_in, const int* in_sizes, int n_in,
                              void* d_out, int out_size)
{
    const float4* attrs = (const float4*)d_in[0];
    const float*  baryw = (const float*)d_in[1];
    const int*    tri   = (const int*)d_in[2];
    float*        out   = (float*)d_out;

    render_kernel<<<NBLOCKS, TPB>>>(attrs, baryw, tri, out);
}

// round 13
// speedup vs baseline: 1.1320x; 1.1320x over previous
#include <cuda_runtime.h>

// Problem constants (fixed by the reference setup)
#define BZ_ 8
#define NF_ 10000
#define D_  16
#define H_  512
#define W_  512
#define HW_ (H_ * W_)        // 262144 = 2^18
#define NPIX (BZ_ * HW_)     // 2097152
#define CH_ (D_ + 1)         // 17 output channels
#define TPB 256
#define PPB 256              // pixels per block: 8 warps x 32 px

__global__ void __launch_bounds__(TPB, 4)     // 64 regs — the proven R5 config
render_kernel(const float4* __restrict__ attrs,   // [BZ*NF, 12] float4 (3 verts x 16 floats)
              const float*  __restrict__ baryw,   // [BZ, H, W, 3]
              const int*    __restrict__ tri,     // [BZ, H, W]
              float*        __restrict__ out)     // [BZ, 17, H, W]
{
    const int lane = threadIdx.x & 31;
    const int q    = lane & 3;                     // channel slice 4q..4q+3
    const int g    = lane >> 2;                    // pixel group within warp
    const int warp = threadIdx.x >> 5;
    const int base = blockIdx.x * PPB + warp * 32; // warp's first pixel (mult of 32)
    const int p0   = base + 4 * g;                 // my 4 consecutive pixels

    // ---- coalesced meta loads: read-once -> streaming (evict-first) ----
    const int4 t4 = __ldcs((const int4*)(tri + p0));               // 4 triangle ids
    const float4* bb = (const float4*)(baryw + 3 * p0);            // 12 floats, 16B aligned
    const float4 b0 = __ldcs(bb + 0);
    const float4 b1 = __ldcs(bb + 1);
    const float4 b2 = __ldcs(bb + 2);

    const int ta[4] = { t4.x, t4.y, t4.z, t4.w };
    // per-slot barycentric weights (flat [px][3] layout)
    const float w0s[4] = { b0.x, b0.w, b1.z, b2.y };
    const float w1s[4] = { b0.y, b1.x, b1.w, b2.z };
    const float w2s[4] = { b0.z, b1.y, b2.x, b2.w };

    float4 acc[4];
    float  vis[4];

    #pragma unroll
    for (int s = 0; s < 4; s++) {
        const int t  = ta[s];
        const float v = (t < 0) ? 0.0f : 1.0f;
        const int  it = (t < 0) ? 0 : t;
        vis[s] = v;

        // gather: 64B-aligned 16B chunks; read-only path, keep L2-resident
        const float4* vp = attrs + it * 12 + q;
        const float4 a = __ldg(vp + 0);
        const float4 b = __ldg(vp + 4);
        const float4 c = __ldg(vp + 8);

        const float w0 = w0s[s] * v;
        const float w1 = w1s[s] * v;
        const float w2 = w2s[s] * v;

        float4 r;
        r.x = fmaf(w0, a.x, fmaf(w1, b.x, w2 * c.x));
        r.y = fmaf(w0, a.y, fmaf(w1, b.y, w2 * c.y));
        r.z = fmaf(w0, a.z, fmaf(w1, b.z, w2 * c.z));
        r.w = fmaf(w0, a.w, fmaf(w1, b.w, w2 * c.w));
        acc[s] = r;
    }

    // ---- stores: register transpose -> one STG.128 per channel plane ----
    // write-once output: streaming stores (evict-first, protect attrs in L2)
    const int n    = base >> 18;                   // base / HW_
    const int pix0 = (base & (HW_ - 1)) + 4 * g;
    float* op = out + (size_t)n * CH_ * HW_ + pix0;

    __stcs((float4*)(op + (size_t)(4 * q + 0) * HW_),
           make_float4(acc[0].x, acc[1].x, acc[2].x, acc[3].x));
    __stcs((float4*)(op + (size_t)(4 * q + 1) * HW_),
           make_float4(acc[0].y, acc[1].y, acc[2].y, acc[3].y));
    __stcs((float4*)(op + (size_t)(4 * q + 2) * HW_),
           make_float4(acc[0].z, acc[1].z, acc[2].z, acc[3].z));
    __stcs((float4*)(op + (size_t)(4 * q + 3) * HW_),
           make_float4(acc[0].w, acc[1].w, acc[2].w, acc[3].w));

    if (q == 0)
        __stcs((float4*)(op + (size_t)D_ * HW_),
               make_float4(vis[0], vis[1], vis[2], vis[3]));   // visibility channel
}

extern "C" void kernel_launch(void* const* d_in, const int* in_sizes, int n_in,
                              void* d_out, int out_size)
{
    const float4* attrs = (const float4*)d_in[0];
    const float*  baryw = (const float*)d_in[1];
    const int*    tri   = (const int*)d_in[2];
    float*        out   = (float*)d_out;

    render_kernel<<<NPIX / PPB, TPB>>>(attrs, baryw, tri, out);
}

// round 14
// speedup vs baseline: 1.2334x; 1.0896x over previous
#include <cuda_runtime.h>
#include <cuda_fp16.h>

// Problem constants (fixed by the reference setup)
#define BZ_ 8
#define NF_ 10000
#define NFACES (BZ_ * NF_)   // 80000
#define D_  16
#define H_  512
#define W_  512
#define HW_ (H_ * W_)        // 262144 = 2^18
#define NPIX (BZ_ * HW_)     // 2097152
#define CH_ (D_ + 1)         // 17 output channels
#define TPB 256
#define PPB 256              // pixels per block: 8 warps x 32 px

// fp16 repacked attrs: 128B per face row, 4 segments of 32B.
// Segment q = [v0c(4q..4q+3), v1c(4q..4q+3), v2c(4q..4q+3), 4 pad halfs]
__device__ __align__(128) __half g_hattr[NFACES * 64];

__global__ void __launch_bounds__(256)
convert_kernel(const float4* __restrict__ attrs)   // [NFACES, 12] float4
{
    const int i = blockIdx.x * blockDim.x + threadIdx.x;   // one float4 each
    if (i >= NFACES * 12) return;
    const int r = i / 12;
    const int j = i - r * 12;          // src float4 j: vertex v=j>>2, quad q=j&3
    const float4 s = attrs[i];
    __half2* dst = (__half2*)(g_hattr + r * 64 + (j & 3) * 16 + (j >> 2) * 4);
    dst[0] = __floats2half2_rn(s.x, s.y);
    dst[1] = __floats2half2_rn(s.z, s.w);
}

__global__ void __launch_bounds__(TPB, 4)     // 64 regs — proven R5 shape
render_kernel(const float*  __restrict__ baryw,   // [BZ, H, W, 3]
              const int*    __restrict__ tri,     // [BZ, H, W]
              float*        __restrict__ out)     // [BZ, 17, H, W]
{
    const int lane = threadIdx.x & 31;
    const int q    = lane & 3;                     // channel slice 4q..4q+3
    const int g    = lane >> 2;                    // pixel group within warp
    const int warp = threadIdx.x >> 5;
    const int base = blockIdx.x * PPB + warp * 32; // warp's first pixel (mult of 32)
    const int p0   = base + 4 * g;                 // my 4 consecutive pixels

    // ---- coalesced meta loads ----
    const int4 t4 = *(const int4*)(tri + p0);                      // 4 triangle ids
    const float4* bb = (const float4*)(baryw + 3 * p0);            // 12 floats, 16B aligned
    const float4 b0 = bb[0], b1 = bb[1], b2 = bb[2];

    const int ta[4] = { t4.x, t4.y, t4.z, t4.w };
    const float w0s[4] = { b0.x, b0.w, b1.z, b2.y };
    const float w1s[4] = { b0.y, b1.x, b1.w, b2.z };
    const float w2s[4] = { b0.z, b1.y, b2.x, b2.w };

    float4 acc[4];
    float  vis[4];

    #pragma unroll
    for (int s = 0; s < 4; s++) {
        const int t  = ta[s];
        const float v = (t < 0) ? 0.0f : 1.0f;
        const int  it = (t < 0) ? 0 : t;
        vis[s] = v;

        // gather: 2 dense 16B loads; all q-lanes of a group hit ONE 128B line
        const uint4* seg = (const uint4*)(g_hattr + it * 64 + q * 16);
        const uint4 u0 = seg[0];     // v0c0-3, v1c0-3 (8 halfs)
        const uint4 u1 = seg[1];     // v2c0-3, pad    (8 halfs)

        const float2 v0a = __half22float2(((const __half2*)&u0)[0]);  // v0 c0,c1
        const float2 v0b = __half22float2(((const __half2*)&u0)[1]);  // v0 c2,c3
        const float2 v1a = __half22float2(((const __half2*)&u0)[2]);  // v1 c0,c1
        const float2 v1b = __half22float2(((const __half2*)&u0)[3]);  // v1 c2,c3
        const float2 v2a = __half22float2(((const __half2*)&u1)[0]);  // v2 c0,c1
        const float2 v2b = __half22float2(((const __half2*)&u1)[1]);  // v2 c2,c3

        const float w0 = w0s[s] * v;
        const float w1 = w1s[s] * v;
        const float w2 = w2s[s] * v;

        float4 r;
        r.x = fmaf(w0, v0a.x, fmaf(w1, v1a.x, w2 * v2a.x));
        r.y = fmaf(w0, v0a.y, fmaf(w1, v1a.y, w2 * v2a.y));
        r.z = fmaf(w0, v0b.x, fmaf(w1, v1b.x, w2 * v2b.x));
        r.w = fmaf(w0, v0b.y, fmaf(w1, v1b.y, w2 * v2b.y));
        acc[s] = r;
    }

    // ---- stores: register transpose -> one STG.128 per channel plane ----
    const int n    = base >> 18;                   // base / HW_
    const int pix0 = (base & (HW_ - 1)) + 4 * g;
    float* op = out + (size_t)n * CH_ * HW_ + pix0;

    *(float4*)(op + (size_t)(4 * q + 0) * HW_) = make_float4(acc[0].x, acc[1].x, acc[2].x, acc[3].x);
    *(float4*)(op + (size_t)(4 * q + 1) * HW_) = make_float4(acc[0].y, acc[1].y, acc[2].y, acc[3].y);
    *(float4*)(op + (size_t)(4 * q + 2) * HW_) = make_float4(acc[0].z, acc[1].z, acc[2].z, acc[3].z);
    *(float4*)(op + (size_t)(4 * q + 3) * HW_) = make_float4(acc[0].w, acc[1].w, acc[2].w, acc[3].w);

    if (q == 0)
        *(float4*)(op + (size_t)D_ * HW_) =
            make_float4(vis[0], vis[1], vis[2], vis[3]);   // visibility channel
}

extern "C" void kernel_launch(void* const* d_in, const int* in_sizes, int n_in,
                              void* d_out, int out_size)
{
    const float4* attrs = (const float4*)d_in[0];
    const float*  baryw = (const float*)d_in[1];
    const int*    tri   = (const int*)d_in[2];
    float*        out   = (float*)d_out;

    convert_kernel<<<(NFACES * 12 + 255) / 256, 256>>>(attrs);
    render_kernel<<<NPIX / PPB, TPB>>>(baryw, tri, out);
}

// round 15
// speedup vs baseline: 1.2865x; 1.0430x over previous
#include <cuda_runtime.h>
#include <cuda_fp16.h>

// Problem constants (fixed by the reference setup)
#define BZ_ 8
#define NF_ 10000
#define NFACES (BZ_ * NF_)   // 80000
#define D_  16
#define H_  512
#define W_  512
#define HW_ (H_ * W_)        // 262144 = 2^18
#define NPIX (BZ_ * HW_)     // 2097152
#define CH_ (D_ + 1)         // 17 output channels
#define TPB 256
#define PPB 256              // pixels per block: 8 warps x 32 px

// fp16 repacked attrs: 128B per face row, 4 segments of 32B.
// Segment q = [v0c(4q..4q+3), v1c(4q..4q+3), v2c(4q..4q+3), 4 pad halfs]
__device__ __align__(128) __half g_hattr[NFACES * 64];

__global__ void __launch_bounds__(256)
convert_kernel(const float4* __restrict__ attrs)   // [NFACES, 12] float4
{
    const int i = blockIdx.x * blockDim.x + threadIdx.x;   // one float4 each
    if (i >= NFACES * 12) return;
    const int r = i / 12;
    const int j = i - r * 12;          // src float4 j: vertex v=j>>2, quad q=j&3
    const float4 s = attrs[i];
    __half2* dst = (__half2*)(g_hattr + r * 64 + (j & 3) * 16 + (j >> 2) * 4);
    dst[0] = __floats2half2_rn(s.x, s.y);
    dst[1] = __floats2half2_rn(s.z, s.w);
}

__global__ void __launch_bounds__(TPB, 5)     // <=51 regs: push occupancy to 62.5% cap
render_kernel(const float*  __restrict__ baryw,   // [BZ, H, W, 3]
              const int*    __restrict__ tri,     // [BZ, H, W]
              float*        __restrict__ out)     // [BZ, 17, H, W]
{
    const int lane = threadIdx.x & 31;
    const int q    = lane & 3;                     // channel slice 4q..4q+3
    const int g    = lane >> 2;                    // pixel group within warp
    const int warp = threadIdx.x >> 5;
    const int base = blockIdx.x * PPB + warp * 32; // warp's first pixel (mult of 32)
    const int p0   = base + 4 * g;                 // my 4 consecutive pixels

    // ---- coalesced meta loads ----
    const int4 t4 = *(const int4*)(tri + p0);                      // 4 triangle ids
    const float4* bb = (const float4*)(baryw + 3 * p0);            // 12 floats, 16B aligned
    const float4 b0 = bb[0], b1 = bb[1], b2 = bb[2];

    const int ta[4] = { t4.x, t4.y, t4.z, t4.w };
    const float w0s[4] = { b0.x, b0.w, b1.z, b2.y };
    const float w1s[4] = { b0.y, b1.x, b1.w, b2.z };
    const float w2s[4] = { b0.z, b1.y, b2.x, b2.w };

    float4 acc[4];
    float  vis[4];

    #pragma unroll
    for (int s = 0; s < 4; s++) {
        const int t  = ta[s];
        const float v = (t < 0) ? 0.0f : 1.0f;
        const int  it = (t < 0) ? 0 : t;
        vis[s] = v;

        // gather: 2 dense 16B loads; all q-lanes of a group hit ONE 128B line
        const uint4* seg = (const uint4*)(g_hattr + it * 64 + q * 16);
        const uint4 u0 = seg[0];     // v0c0-3, v1c0-3 (8 halfs)
        const uint4 u1 = seg[1];     // v2c0-3, pad    (8 halfs)

        const float2 v0a = __half22float2(((const __half2*)&u0)[0]);  // v0 c0,c1
        const float2 v0b = __half22float2(((const __half2*)&u0)[1]);  // v0 c2,c3
        const float2 v1a = __half22float2(((const __half2*)&u0)[2]);  // v1 c0,c1
        const float2 v1b = __half22float2(((const __half2*)&u0)[3]);  // v1 c2,c3
        const float2 v2a = __half22float2(((const __half2*)&u1)[0]);  // v2 c0,c1
        const float2 v2b = __half22float2(((const __half2*)&u1)[1]);  // v2 c2,c3

        const float w0 = w0s[s] * v;
        const float w1 = w1s[s] * v;
        const float w2 = w2s[s] * v;

        float4 r;
        r.x = fmaf(w0, v0a.x, fmaf(w1, v1a.x, w2 * v2a.x));
        r.y = fmaf(w0, v0a.y, fmaf(w1, v1a.y, w2 * v2a.y));
        r.z = fmaf(w0, v0b.x, fmaf(w1, v1b.x, w2 * v2b.x));
        r.w = fmaf(w0, v0b.y, fmaf(w1, v1b.y, w2 * v2b.y));
        acc[s] = r;
    }

    // ---- stores: register transpose -> one STG.128 per channel plane ----
    const int n    = base >> 18;                   // base / HW_
    const int pix0 = (base & (HW_ - 1)) + 4 * g;
    float* op = out + (size_t)n * CH_ * HW_ + pix0;

    *(float4*)(op + (size_t)(4 * q + 0) * HW_) = make_float4(acc[0].x, acc[1].x, acc[2].x, acc[3].x);
    *(float4*)(op + (size_t)(4 * q + 1) * HW_) = make_float4(acc[0].y, acc[1].y, acc[2].y, acc[3].y);
    *(float4*)(op + (size_t)(4 * q + 2) * HW_) = make_float4(acc[0].z, acc[1].z, acc[2].z, acc[3].z);
    *(float4*)(op + (size_t)(4 * q + 3) * HW_) = make_float4(acc[0].w, acc[1].w, acc[2].w, acc[3].w);

    if (q == 0)
        *(float4*)(op + (size_t)D_ * HW_) =
            make_float4(vis[0], vis[1], vis[2], vis[3]);   // visibility channel
}

extern "C" void kernel_launch(void* const* d_in, const int* in_sizes, int n_in,
                              void* d_out, int out_size)
{
    const float4* attrs = (const float4*)d_in[0];
    const float*  baryw = (const float*)d_in[1];
    const int*    tri   = (const int*)d_in[2];
    float*        out   = (float*)d_out;

    convert_kernel<<<(NFACES * 12 + 255) / 256, 256>>>(attrs);
    render_kernel<<<NPIX / PPB, TPB>>>(baryw, tri, out);
}